// round 6
// baseline (speedup 1.0000x reference)
#include <cuda_runtime.h>
#include <cuda_bf16.h>
#include <cstdint>
#include <math.h>

// phi (64,256) row-major, X (256,K), Y (64,K); k = idx+1 active columns.
constexpr int NROW = 256;   // rows of X = cols of phi
constexpr int MDIM = 64;    // rows of phi / Y
constexpr int NT   = 128;   // columns per CTA tile
constexpr int TPB  = 256;   // 8 warps

// ---- SMEM byte offsets (all row strides = 16B mod 128B -> conflict-free frags) ----
constexpr int PHA_HI = 0;       // phi  [64][264] bf16 (row-major, k-contig)
constexpr int PHA_LO = 33792;
constexpr int PHT_HI = 67584;   // phiT [256][72] bf16 (n-major, k=phi-row contig)
constexpr int PHT_LO = 104448;
constexpr int XS_HI  = 141312;  // X chunk [128 cols][72] bf16 (col-major, 64 k + pad)
constexpr int XS_LO  = 159744;
constexpr int RS_HI  = 178176;  // resid [128 cols][72] bf16
constexpr int RS_LO  = 196608;
constexpr int SMEM_TOTAL = 215040;

constexpr int PHA_S32 = 132;    // u32 strides
constexpr int PHT_S32 = 36;
constexpr int XS_S32  = 36;
constexpr int RS_S32  = 36;

__device__ __forceinline__ void bf16_split(float v, uint16_t& hi, uint16_t& lo) {
    __nv_bfloat16 h = __float2bfloat16_rn(v);
    __nv_bfloat16 l = __float2bfloat16_rn(v - __bfloat162float(h));
    hi = __bfloat16_as_ushort(h);
    lo = __bfloat16_as_ushort(l);
}

// mma.sync m16n8k16 row.col f32 += bf16*bf16 (standard PTX, compute_80+)
#define MMA_BF16(c, a, b0, b1)                                                  \
    asm volatile("mma.sync.aligned.m16n8k16.row.col.f32.bf16.bf16.f32 "         \
        "{%0,%1,%2,%3}, {%4,%5,%6,%7}, {%8,%9}, {%0,%1,%2,%3};"                 \
        : "+f"((c)[0]), "+f"((c)[1]), "+f"((c)[2]), "+f"((c)[3])                \
        : "r"((a)[0]), "r"((a)[1]), "r"((a)[2]), "r"((a)[3]), "r"(b0), "r"(b1))

extern __shared__ char smem[];

__global__ __launch_bounds__(TPB)
void ista_hmma_kernel(const float* __restrict__ phi,
                      const float* __restrict__ X,
                      const float* __restrict__ Y,
                      const float* __restrict__ step,
                      const int*   __restrict__ idxp,
                      float*       __restrict__ outX,
                      int K)
{
    const int tid  = threadIdx.x;
    const int w    = tid >> 5;
    const int lane = tid & 31;
    const int g    = lane >> 2;   // group row
    const int tg   = lane & 3;    // thread-in-group
    const int base = blockIdx.x * NT;
    const int kact = *idxp + 1;

    // ---------------- passthrough tiles ----------------
    if (base >= kact) {
        const int col = base + (tid & 127);
        if (col < K) {
            for (int n = (tid >> 7); n < NROW; n += 2)
                outX[(size_t)n * K + col] = X[(size_t)n * K + col];
        }
        return;
    }

    const float s = *step;

    uint32_t* pha_hi = (uint32_t*)(smem + PHA_HI);
    uint32_t* pha_lo = (uint32_t*)(smem + PHA_LO);
    uint32_t* pht_hi = (uint32_t*)(smem + PHT_HI);
    uint32_t* pht_lo = (uint32_t*)(smem + PHT_LO);
    uint32_t* xs_hi  = (uint32_t*)(smem + XS_HI);
    uint32_t* xs_lo  = (uint32_t*)(smem + XS_LO);
    uint32_t* rs_hi  = (uint32_t*)(smem + RS_HI);
    uint32_t* rs_lo  = (uint32_t*)(smem + RS_LO);
    uint16_t* rs_hi16 = (uint16_t*)(smem + RS_HI);
    uint16_t* rs_lo16 = (uint16_t*)(smem + RS_LO);

    // ---------------- stage phi (both orientations, bf16 splits) ----------------
    // phiA: [m][k] pairs over k
    for (int it = tid; it < MDIM * 128; it += TPB) {
        const int m = it >> 7, kp = it & 127;
        const float2 v = *(const float2*)(phi + m * NROW + 2 * kp);
        uint16_t h0, l0, h1, l1;
        bf16_split(v.x, h0, l0);
        bf16_split(v.y, h1, l1);
        pha_hi[m * PHA_S32 + kp] = (uint32_t)h0 | ((uint32_t)h1 << 16);
        pha_lo[m * PHA_S32 + kp] = (uint32_t)l0 | ((uint32_t)l1 << 16);
    }
    // phiT: [n][m] pairs over m
    for (int it = tid; it < NROW * 32; it += TPB) {
        const int n = it & 255, mp = it >> 8;
        const float a = phi[(2 * mp) * NROW + n];
        const float b = phi[(2 * mp + 1) * NROW + n];
        uint16_t h0, l0, h1, l1;
        bf16_split(a, h0, l0);
        bf16_split(b, h1, l1);
        pht_hi[n * PHT_S32 + mp] = (uint32_t)h0 | ((uint32_t)h1 << 16);
        pht_lo[n * PHT_S32 + mp] = (uint32_t)l0 | ((uint32_t)l1 << 16);
    }

    // ================= GEMM A: R(64 x 128) = phi . Xtile, K in 4 chunks =================
    // warp w: m-tile = 16*(w&3), n-range = 64*(w>>2) .. +64  (8 n8-tiles)
    const int mbase  = 16 * (w & 3);
    const int nbase0 = 64 * (w >> 2);
    float cA[8][4];
    #pragma unroll
    for (int nt = 0; nt < 8; ++nt)
        #pragma unroll
        for (int q = 0; q < 4; ++q) cA[nt][q] = 0.0f;

    #pragma unroll 1
    for (int chunk = 0; chunk < 4; ++chunk) {
        __syncthreads();   // prior chunk consumed (and phi staged, first pass)
        // stage Xs: cols 0..127, k-pairs 0..31 of this 64-row chunk
        for (int it = tid; it < 128 * 32; it += TPB) {
            const int col = it & 127, kp = it >> 7;
            const int gn = chunk * 64 + 2 * kp;
            int gc = base + col; gc = (gc < K) ? gc : (K - 1);
            const float x0 = X[(size_t)gn * K + gc];
            const float x1 = X[(size_t)(gn + 1) * K + gc];
            uint16_t h0, l0, h1, l1;
            bf16_split(x0, h0, l0);
            bf16_split(x1, h1, l1);
            xs_hi[col * XS_S32 + kp] = (uint32_t)h0 | ((uint32_t)h1 << 16);
            xs_lo[col * XS_S32 + kp] = (uint32_t)l0 | ((uint32_t)l1 << 16);
        }
        __syncthreads();

        #pragma unroll
        for (int ks = 0; ks < 4; ++ks) {
            const int kh = chunk * 32 + ks * 8 + tg;  // u32 k-index into phiA
            uint32_t ah[4], al[4];
            ah[0] = pha_hi[(mbase + g) * PHA_S32 + kh];
            ah[1] = pha_hi[(mbase + g + 8) * PHA_S32 + kh];
            ah[2] = pha_hi[(mbase + g) * PHA_S32 + kh + 4];
            ah[3] = pha_hi[(mbase + g + 8) * PHA_S32 + kh + 4];
            al[0] = pha_lo[(mbase + g) * PHA_S32 + kh];
            al[1] = pha_lo[(mbase + g + 8) * PHA_S32 + kh];
            al[2] = pha_lo[(mbase + g) * PHA_S32 + kh + 4];
            al[3] = pha_lo[(mbase + g + 8) * PHA_S32 + kh + 4];
            #pragma unroll
            for (int nt = 0; nt < 8; ++nt) {
                const int n  = nbase0 + nt * 8 + g;
                const int kk = ks * 8 + tg;
                const uint32_t bh0 = xs_hi[n * XS_S32 + kk];
                const uint32_t bh1 = xs_hi[n * XS_S32 + kk + 4];
                const uint32_t bl0 = xs_lo[n * XS_S32 + kk];
                const uint32_t bl1 = xs_lo[n * XS_S32 + kk + 4];
                MMA_BF16(cA[nt], ah, bh0, bh1);
                MMA_BF16(cA[nt], ah, bl0, bl1);
                MMA_BF16(cA[nt], al, bh0, bh1);
            }
        }
    }

    // ---- epilogue A: r = s*(y - R) -> bf16 split -> Rs[n][m] ----
    #pragma unroll
    for (int nt = 0; nt < 8; ++nt) {
        const int nloc = nbase0 + nt * 8 + 2 * tg;
        int col0 = base + nloc; col0 = (col0 < K - 1) ? col0 : (K - 2);
        const int m0 = mbase + g, m1 = m0 + 8;
        const float2 y0 = *(const float2*)(Y + (size_t)m0 * K + col0);
        const float2 y1 = *(const float2*)(Y + (size_t)m1 * K + col0);
        const float r00 = s * (y0.x - cA[nt][0]);
        const float r01 = s * (y0.y - cA[nt][1]);
        const float r10 = s * (y1.x - cA[nt][2]);
        const float r11 = s * (y1.y - cA[nt][3]);
        uint16_t h, l;
        bf16_split(r00, h, l); rs_hi16[nloc * 72 + m0] = h; rs_lo16[nloc * 72 + m0] = l;
        bf16_split(r01, h, l); rs_hi16[(nloc + 1) * 72 + m0] = h; rs_lo16[(nloc + 1) * 72 + m0] = l;
        bf16_split(r10, h, l); rs_hi16[nloc * 72 + m1] = h; rs_lo16[nloc * 72 + m1] = l;
        bf16_split(r11, h, l); rs_hi16[(nloc + 1) * 72 + m1] = h; rs_lo16[(nloc + 1) * 72 + m1] = l;
    }
    __syncthreads();

    // ================= GEMM B: corr(256 x 128) = phiT . R, K = 64 =================
    // warp w: m-tiles {2w, 2w+1} (Xrows 32w..32w+31), n in 2 passes of 64.
    #pragma unroll 1
    for (int pass = 0; pass < 2; ++pass) {
        const int nb = pass * 64;
        float cB[2][8][4];
        #pragma unroll
        for (int mt = 0; mt < 2; ++mt)
            #pragma unroll
            for (int nt = 0; nt < 8; ++nt)
                #pragma unroll
                for (int q = 0; q < 4; ++q) cB[mt][nt][q] = 0.0f;

        #pragma unroll
        for (int ks = 0; ks < 4; ++ks) {
            uint32_t ath[2][4], atl[2][4];
            #pragma unroll
            for (int mt = 0; mt < 2; ++mt) {
                const int row = 32 * w + 16 * mt + g;
                const int kh  = ks * 8 + tg;
                ath[mt][0] = pht_hi[row * PHT_S32 + kh];
                ath[mt][1] = pht_hi[(row + 8) * PHT_S32 + kh];
                ath[mt][2] = pht_hi[row * PHT_S32 + kh + 4];
                ath[mt][3] = pht_hi[(row + 8) * PHT_S32 + kh + 4];
                atl[mt][0] = pht_lo[row * PHT_S32 + kh];
                atl[mt][1] = pht_lo[(row + 8) * PHT_S32 + kh];
                atl[mt][2] = pht_lo[row * PHT_S32 + kh + 4];
                atl[mt][3] = pht_lo[(row + 8) * PHT_S32 + kh + 4];
            }
            #pragma unroll
            for (int nt = 0; nt < 8; ++nt) {
                const int n  = nb + nt * 8 + g;
                const int kk = ks * 8 + tg;
                const uint32_t bh0 = rs_hi[n * RS_S32 + kk];
                const uint32_t bh1 = rs_hi[n * RS_S32 + kk + 4];
                const uint32_t bl0 = rs_lo[n * RS_S32 + kk];
                const uint32_t bl1 = rs_lo[n * RS_S32 + kk + 4];
                #pragma unroll
                for (int mt = 0; mt < 2; ++mt) {
                    MMA_BF16(cB[mt][nt], ath[mt], bh0, bh1);
                    MMA_BF16(cB[mt][nt], ath[mt], bl0, bl1);
                    MMA_BF16(cB[mt][nt], atl[mt], bh0, bh1);
                }
            }
        }

        // ---- epilogue B: out = thresh(X + corr), passthrough beyond kact ----
        #pragma unroll
        for (int mt = 0; mt < 2; ++mt) {
            #pragma unroll
            for (int nt = 0; nt < 8; ++nt) {
                const int col0 = base + nb + nt * 8 + 2 * tg;
                if (col0 + 1 >= K) continue;
                const int r0 = 32 * w + 16 * mt + g;
                const int r1 = r0 + 8;
                const float2 x0 = *(const float2*)(X + (size_t)r0 * K + col0);
                const float2 x1 = *(const float2*)(X + (size_t)r1 * K + col0);
                float u00 = x0.x + cB[mt][nt][0];
                float u01 = x0.y + cB[mt][nt][1];
                float u10 = x1.x + cB[mt][nt][2];
                float u11 = x1.y + cB[mt][nt][3];
                u00 = (fabsf(u00) > 0.1f) ? u00 : 0.0f;
                u01 = (fabsf(u01) > 0.1f) ? u01 : 0.0f;
                u10 = (fabsf(u10) > 0.1f) ? u10 : 0.0f;
                u11 = (fabsf(u11) > 0.1f) ? u11 : 0.0f;
                const bool a0 = (col0 < kact), a1 = (col0 + 1 < kact);
                float2 o0, o1;
                o0.x = a0 ? u00 : x0.x;  o0.y = a1 ? u01 : x0.y;
                o1.x = a0 ? u10 : x1.x;  o1.y = a1 ? u11 : x1.y;
                *(float2*)(outX + (size_t)r0 * K + col0) = o0;
                *(float2*)(outX + (size_t)r1 * K + col0) = o1;
            }
        }
    }
}

extern "C" void kernel_launch(void* const* d_in, const int* in_sizes, int n_in,
                              void* d_out, int out_size)
{
    const float* phi  = (const float*)d_in[0];
    const float* X    = (const float*)d_in[1];
    const float* Y    = (const float*)d_in[2];
    const float* step = (const float*)d_in[3];
    const int*   idx  = (const int*)d_in[4];

    const int phiN = in_sizes[0];
    const int XN   = in_sizes[1];
    const int K    = XN / NROW;

    float* outX = (float*)d_out;
    if (out_size == phiN + XN) {
        cudaMemcpyAsync(d_out, phi, (size_t)phiN * sizeof(float),
                        cudaMemcpyDeviceToDevice, 0);
        outX = (float*)d_out + phiN;
    }

    cudaFuncSetAttribute(ista_hmma_kernel,
                         cudaFuncAttributeMaxDynamicSharedMemorySize, SMEM_TOTAL);

    const int grid = (K + NT - 1) / NT;
    ista_hmma_kernel<<<grid, TPB, SMEM_TOTAL>>>(phi, X, Y, step, idx, outX, K);
}

// round 7
// speedup vs baseline: 1.4517x; 1.4517x over previous
#include <cuda_runtime.h>
#include <cuda_bf16.h>
#include <cstdint>
#include <math.h>

// phi (64,256) row-major, X (256,K), Y (64,K); k = idx+1 active columns.
constexpr int NROW = 256;
constexpr int MDIM = 64;
constexpr int NT   = 128;   // columns per CTA tile
constexpr int TPB  = 256;   // 8 warps

// ---- SMEM map (row strides = 16B mod 128B -> conflict-free frags) ----
constexpr int PHA_HI = 0;       // phi [64][264] bf16, native row-major (k-contig)
constexpr int PHA_LO = 33792;
constexpr int XS_HI  = 67584;   // X chunk [128 cols][72] bf16; ALIASED by resid after GEMM A
constexpr int XS_LO  = 86016;
constexpr int RS_HI  = XS_HI;   // resid [128 cols][72] bf16 (m-contig)
constexpr int RS_LO  = XS_LO;
constexpr int SMEM_TOTAL = 104448 + 128;

constexpr int PHA_S32 = 132;    // u32 strides
constexpr int PHA_SB  = 528;    // byte stride
constexpr int XS_S32  = 36;
constexpr int RS_S32  = 36;

__device__ __forceinline__ void bf16_split(float v, uint16_t& hi, uint16_t& lo) {
    __nv_bfloat16 h = __float2bfloat16_rn(v);
    __nv_bfloat16 l = __float2bfloat16_rn(v - __bfloat162float(h));
    hi = __bfloat16_as_ushort(h);
    lo = __bfloat16_as_ushort(l);
}

__device__ __forceinline__ uint32_t smem_u32(const void* p) {
    uint32_t a;
    asm("{ .reg .u64 t; cvta.to.shared.u64 t, %1; cvt.u32.u64 %0, t; }" : "=r"(a) : "l"(p));
    return a;
}

// mma.sync m16n8k16 row.col f32 += bf16*bf16 (compute_80+)
#define MMA_BF16(c, a, b0, b1)                                                  \
    asm volatile("mma.sync.aligned.m16n8k16.row.col.f32.bf16.bf16.f32 "         \
        "{%0,%1,%2,%3}, {%4,%5,%6,%7}, {%8,%9}, {%0,%1,%2,%3};"                 \
        : "+f"((c)[0]), "+f"((c)[1]), "+f"((c)[2]), "+f"((c)[3])                \
        : "r"((a)[0]), "r"((a)[1]), "r"((a)[2]), "r"((a)[3]), "r"(b0), "r"(b1))

// transposed 4x 8x8 b16 tile load (compute_75+): yields phiT A-fragments from native phi
#define LDMX4T(r, addr)                                                         \
    asm volatile("ldmatrix.sync.aligned.m8n8.x4.trans.shared.b16 "              \
        "{%0,%1,%2,%3}, [%4];"                                                  \
        : "=r"((r)[0]), "=r"((r)[1]), "=r"((r)[2]), "=r"((r)[3]) : "r"(addr))

extern __shared__ char smem[];

__global__ __launch_bounds__(TPB, 2)
void ista_hmma_kernel(const float* __restrict__ phi,
                      const float* __restrict__ X,
                      const float* __restrict__ Y,
                      const float* __restrict__ step,
                      const int*   __restrict__ idxp,
                      float*       __restrict__ outX,
                      int K)
{
    const int tid  = threadIdx.x;
    const int w    = tid >> 5;
    const int lane = tid & 31;
    const int g    = lane >> 2;
    const int tg   = lane & 3;
    const int base = blockIdx.x * NT;
    const int kact = *idxp + 1;

    // ---------------- passthrough tiles ----------------
    if (base >= kact) {
        const int col = base + (tid & 127);
        if (col < K) {
            for (int n = (tid >> 7); n < NROW; n += 2)
                outX[(size_t)n * K + col] = X[(size_t)n * K + col];
        }
        return;
    }

    const float s = *step;

    uint32_t* pha_hi = (uint32_t*)(smem + PHA_HI);
    uint32_t* pha_lo = (uint32_t*)(smem + PHA_LO);
    uint32_t* xs_hi  = (uint32_t*)(smem + XS_HI);
    uint32_t* xs_lo  = (uint32_t*)(smem + XS_LO);
    uint32_t* rs_hi  = (uint32_t*)(smem + RS_HI);
    uint32_t* rs_lo  = (uint32_t*)(smem + RS_LO);
    uint16_t* rs_hi16 = (uint16_t*)(smem + RS_HI);
    uint16_t* rs_lo16 = (uint16_t*)(smem + RS_LO);

    // ---------------- stage phi (native orientation only, hi/lo splits) ----------------
    for (int it = tid; it < MDIM * 128; it += TPB) {
        const int m = it >> 7, kp = it & 127;
        const float2 v = *(const float2*)(phi + m * NROW + 2 * kp);
        uint16_t h0, l0, h1, l1;
        bf16_split(v.x, h0, l0);
        bf16_split(v.y, h1, l1);
        pha_hi[m * PHA_S32 + kp] = (uint32_t)h0 | ((uint32_t)h1 << 16);
        pha_lo[m * PHA_S32 + kp] = (uint32_t)l0 | ((uint32_t)l1 << 16);
    }

    // ================= GEMM A: R(64 x 128) = phi . Xtile, K in 4 chunks =================
    const int mbase  = 16 * (w & 3);
    const int nbase0 = 64 * (w >> 2);
    float cA[8][4];
    #pragma unroll
    for (int nt = 0; nt < 8; ++nt)
        #pragma unroll
        for (int q = 0; q < 4; ++q) cA[nt][q] = 0.0f;

    #pragma unroll 1
    for (int chunk = 0; chunk < 4; ++chunk) {
        __syncthreads();
        for (int it = tid; it < 128 * 32; it += TPB) {
            const int col = it & 127, kp = it >> 7;
            const int gn = chunk * 64 + 2 * kp;
            int gc = base + col; gc = (gc < K) ? gc : (K - 1);
            const float x0 = X[(size_t)gn * K + gc];
            const float x1 = X[(size_t)(gn + 1) * K + gc];
            uint16_t h0, l0, h1, l1;
            bf16_split(x0, h0, l0);
            bf16_split(x1, h1, l1);
            xs_hi[col * XS_S32 + kp] = (uint32_t)h0 | ((uint32_t)h1 << 16);
            xs_lo[col * XS_S32 + kp] = (uint32_t)l0 | ((uint32_t)l1 << 16);
        }
        __syncthreads();

        #pragma unroll
        for (int ks = 0; ks < 4; ++ks) {
            const int kh = chunk * 32 + ks * 8 + tg;
            uint32_t ah[4], al[4];
            ah[0] = pha_hi[(mbase + g) * PHA_S32 + kh];
            ah[1] = pha_hi[(mbase + g + 8) * PHA_S32 + kh];
            ah[2] = pha_hi[(mbase + g) * PHA_S32 + kh + 4];
            ah[3] = pha_hi[(mbase + g + 8) * PHA_S32 + kh + 4];
            al[0] = pha_lo[(mbase + g) * PHA_S32 + kh];
            al[1] = pha_lo[(mbase + g + 8) * PHA_S32 + kh];
            al[2] = pha_lo[(mbase + g) * PHA_S32 + kh + 4];
            al[3] = pha_lo[(mbase + g + 8) * PHA_S32 + kh + 4];
            #pragma unroll
            for (int nt = 0; nt < 8; ++nt) {
                const int n  = nbase0 + nt * 8 + g;
                const int kk = ks * 8 + tg;
                const uint32_t bh0 = xs_hi[n * XS_S32 + kk];
                const uint32_t bh1 = xs_hi[n * XS_S32 + kk + 4];
                const uint32_t bl0 = xs_lo[n * XS_S32 + kk];
                const uint32_t bl1 = xs_lo[n * XS_S32 + kk + 4];
                MMA_BF16(cA[nt], ah, bh0, bh1);
                MMA_BF16(cA[nt], ah, bl0, bl1);
                MMA_BF16(cA[nt], al, bh0, bh1);
            }
        }
    }
    __syncthreads();   // all warps done reading XS before resid overwrites it

    // ---- epilogue A: r = s*(y - R) -> bf16 split -> Rs[n][m] (aliases XS) ----
    #pragma unroll
    for (int nt = 0; nt < 8; ++nt) {
        const int nloc = nbase0 + nt * 8 + 2 * tg;
        int col0 = base + nloc; col0 = (col0 < K - 1) ? col0 : (K - 2);
        const int m0 = mbase + g, m1 = m0 + 8;
        const float2 y0 = *(const float2*)(Y + (size_t)m0 * K + col0);
        const float2 y1 = *(const float2*)(Y + (size_t)m1 * K + col0);
        const float r00 = s * (y0.x - cA[nt][0]);
        const float r01 = s * (y0.y - cA[nt][1]);
        const float r10 = s * (y1.x - cA[nt][2]);
        const float r11 = s * (y1.y - cA[nt][3]);
        uint16_t h, l;
        bf16_split(r00, h, l); rs_hi16[nloc * 72 + m0] = h; rs_lo16[nloc * 72 + m0] = l;
        bf16_split(r01, h, l); rs_hi16[(nloc + 1) * 72 + m0] = h; rs_lo16[(nloc + 1) * 72 + m0] = l;
        bf16_split(r10, h, l); rs_hi16[nloc * 72 + m1] = h; rs_lo16[nloc * 72 + m1] = l;
        bf16_split(r11, h, l); rs_hi16[(nloc + 1) * 72 + m1] = h; rs_lo16[(nloc + 1) * 72 + m1] = l;
    }
    __syncthreads();

    // ================= GEMM B: corr(256 x 128) = phiT . R, K = 64 =================
    // phiT A-fragments come from NATIVE phi layout via ldmatrix.x4.trans.
    // lane address: phi_row(k) = k0 + (lane&7) + ((lane&16)>>1), phi_col(m) += (lane&8).
    const uint32_t pha_hi_b = smem_u32(smem + PHA_HI);
    const uint32_t pha_lo_b = smem_u32(smem + PHA_LO);
    const int lrow = (lane & 7) + ((lane & 16) >> 1);
    const int lcol = (lane & 8);

    #pragma unroll 1
    for (int pass = 0; pass < 2; ++pass) {
        const int nb = pass * 64;
        float cB[2][8][4];
        #pragma unroll
        for (int mt = 0; mt < 2; ++mt)
            #pragma unroll
            for (int nt = 0; nt < 8; ++nt)
                #pragma unroll
                for (int q = 0; q < 4; ++q) cB[mt][nt][q] = 0.0f;

        #pragma unroll
        for (int ks = 0; ks < 4; ++ks) {
            const int k0 = ks * 16;   // phi row base for this k-step
            uint32_t ath[2][4], atl[2][4];
            #pragma unroll
            for (int mt = 0; mt < 2; ++mt) {
                const int m0 = 32 * w + 16 * mt;   // phi col base (= GEMM-B m)
                const uint32_t off = (uint32_t)((k0 + lrow) * PHA_SB + (m0 + lcol) * 2);
                LDMX4T(ath[mt], pha_hi_b + off);
                LDMX4T(atl[mt], pha_lo_b + off);
            }
            #pragma unroll
            for (int nt = 0; nt < 8; ++nt) {
                const int n  = nb + nt * 8 + g;
                const int kk = ks * 8 + tg;
                const uint32_t bh0 = rs_hi[n * RS_S32 + kk];
                const uint32_t bh1 = rs_hi[n * RS_S32 + kk + 4];
                const uint32_t bl0 = rs_lo[n * RS_S32 + kk];
                const uint32_t bl1 = rs_lo[n * RS_S32 + kk + 4];
                #pragma unroll
                for (int mt = 0; mt < 2; ++mt) {
                    MMA_BF16(cB[mt][nt], ath[mt], bh0, bh1);
                    MMA_BF16(cB[mt][nt], ath[mt], bl0, bl1);
                    MMA_BF16(cB[mt][nt], atl[mt], bh0, bh1);
                }
            }
        }

        // ---- epilogue B: out = thresh(X + corr), passthrough beyond kact ----
        #pragma unroll
        for (int mt = 0; mt < 2; ++mt) {
            #pragma unroll
            for (int nt = 0; nt < 8; ++nt) {
                const int col0 = base + nb + nt * 8 + 2 * tg;
                if (col0 + 1 >= K) continue;
                const int r0 = 32 * w + 16 * mt + g;
                const int r1 = r0 + 8;
                const float2 x0 = *(const float2*)(X + (size_t)r0 * K + col0);
                const float2 x1 = *(const float2*)(X + (size_t)r1 * K + col0);
                float u00 = x0.x + cB[mt][nt][0];
                float u01 = x0.y + cB[mt][nt][1];
                float u10 = x1.x + cB[mt][nt][2];
                float u11 = x1.y + cB[mt][nt][3];
                u00 = (fabsf(u00) > 0.1f) ? u00 : 0.0f;
                u01 = (fabsf(u01) > 0.1f) ? u01 : 0.0f;
                u10 = (fabsf(u10) > 0.1f) ? u10 : 0.0f;
                u11 = (fabsf(u11) > 0.1f) ? u11 : 0.0f;
                const bool a0 = (col0 < kact), a1 = (col0 + 1 < kact);
                float2 o0, o1;
                o0.x = a0 ? u00 : x0.x;  o0.y = a1 ? u01 : x0.y;
                o1.x = a0 ? u10 : x1.x;  o1.y = a1 ? u11 : x1.y;
                *(float2*)(outX + (size_t)r0 * K + col0) = o0;
                *(float2*)(outX + (size_t)r1 * K + col0) = o1;
            }
        }
    }
}

extern "C" void kernel_launch(void* const* d_in, const int* in_sizes, int n_in,
                              void* d_out, int out_size)
{
    const float* phi  = (const float*)d_in[0];
    const float* X    = (const float*)d_in[1];
    const float* Y    = (const float*)d_in[2];
    const float* step = (const float*)d_in[3];
    const int*   idx  = (const int*)d_in[4];

    const int phiN = in_sizes[0];
    const int XN   = in_sizes[1];
    const int K    = XN / NROW;

    float* outX = (float*)d_out;
    if (out_size == phiN + XN) {
        cudaMemcpyAsync(d_out, phi, (size_t)phiN * sizeof(float),
                        cudaMemcpyDeviceToDevice, 0);
        outX = (float*)d_out + phiN;
    }

    cudaFuncSetAttribute(ista_hmma_kernel,
                         cudaFuncAttributeMaxDynamicSharedMemorySize, SMEM_TOTAL);

    const int grid = (K + NT - 1) / NT;
    ista_hmma_kernel<<<grid, TPB, SMEM_TOTAL>>>(phi, X, Y, step, idx, outX, K);
}

// round 8
// speedup vs baseline: 1.4733x; 1.0148x over previous
#include <cuda_runtime.h>
#include <cuda_bf16.h>
#include <cstdint>
#include <math.h>

// phi (64,256) row-major, X (256,K), Y (64,K); k = idx+1 active columns.
constexpr int NROW = 256;
constexpr int MDIM = 64;
constexpr int NT   = 128;   // columns per CTA tile
constexpr int TPB  = 256;   // 8 warps

// ---- SMEM map ----
constexpr int PHA_HI = 0;       // phi [64][264] bf16 row-major (k-contig), 528B row stride
constexpr int PHA_LO = 33792;
constexpr int POOL   = 67584;
constexpr int XS_HI  = POOL;            // X chunk [128 cols][20 u32] (32 rows -> 16 u32 + pad)
constexpr int XS_LO  = POOL + 10240;
constexpr int RS_HI  = POOL;            // resid [128 cols][36 u32]; aliases XS (time-disjoint)
constexpr int RS_LO  = POOL + 18432;
constexpr int SMEM_TOTAL = POOL + 36864 + 128;   // 104576

constexpr int PHA_SB = 528;    // phi row stride bytes
constexpr int XS_S32 = 20;     // u32 stride (80 B)
constexpr int XS_SB  = 80;
constexpr int RS_S32 = 36;     // u32 stride (144 B)
constexpr int RS_SB  = 144;

constexpr int CHUNK = 32;      // X rows per staging chunk
constexpr int NCHUNK = NROW / CHUNK;  // 8

__device__ __forceinline__ void bf16_split(float v, uint16_t& hi, uint16_t& lo) {
    __nv_bfloat16 h = __float2bfloat16_rn(v);
    __nv_bfloat16 l = __float2bfloat16_rn(v - __bfloat162float(h));
    hi = __bfloat16_as_ushort(h);
    lo = __bfloat16_as_ushort(l);
}
__device__ __forceinline__ uint32_t smem_u32(const void* p) {
    uint32_t a;
    asm("{ .reg .u64 t; cvta.to.shared.u64 t, %1; cvt.u32.u64 %0, t; }" : "=r"(a) : "l"(p));
    return a;
}

// mma.sync m16n8k16 row.col f32 += bf16*bf16 (compute_80+)
#define MMA_BF16(c, a, b0, b1)                                                  \
    asm volatile("mma.sync.aligned.m16n8k16.row.col.f32.bf16.bf16.f32 "         \
        "{%0,%1,%2,%3}, {%4,%5,%6,%7}, {%8,%9}, {%0,%1,%2,%3};"                 \
        : "+f"((c)[0]), "+f"((c)[1]), "+f"((c)[2]), "+f"((c)[3])                \
        : "r"((a)[0]), "r"((a)[1]), "r"((a)[2]), "r"((a)[3]), "r"(b0), "r"(b1))

#define LDMX4(r, addr)                                                          \
    asm volatile("ldmatrix.sync.aligned.m8n8.x4.shared.b16 {%0,%1,%2,%3}, [%4];"\
        : "=r"((r)[0]), "=r"((r)[1]), "=r"((r)[2]), "=r"((r)[3]) : "r"(addr))
#define LDMX4T(r, addr)                                                         \
    asm volatile("ldmatrix.sync.aligned.m8n8.x4.trans.shared.b16 {%0,%1,%2,%3}, [%4];" \
        : "=r"((r)[0]), "=r"((r)[1]), "=r"((r)[2]), "=r"((r)[3]) : "r"(addr))
#define LDMX2(r, addr)                                                          \
    asm volatile("ldmatrix.sync.aligned.m8n8.x2.shared.b16 {%0,%1}, [%2];"      \
        : "=r"((r)[0]), "=r"((r)[1]) : "r"(addr))

extern __shared__ char smem[];

__global__ __launch_bounds__(TPB, 2)
void ista_hmma_kernel(const float* __restrict__ phi,
                      const float* __restrict__ X,
                      const float* __restrict__ Y,
                      const float* __restrict__ step,
                      const int*   __restrict__ idxp,
                      float*       __restrict__ outX,
                      int K)
{
    const int tid  = threadIdx.x;
    const int w    = tid >> 5;
    const int lane = tid & 31;
    const int g    = lane >> 2;
    const int tg   = lane & 3;
    const int base = blockIdx.x * NT;
    const int kact = *idxp + 1;

    // ---------------- passthrough tiles ----------------
    if (base >= kact) {
        const int col = base + (tid & 127);
        if (col < K) {
            for (int n = (tid >> 7); n < NROW; n += 2)
                outX[(size_t)n * K + col] = X[(size_t)n * K + col];
        }
        return;
    }

    const float s = *step;

    uint32_t* pha_hi = (uint32_t*)(smem + PHA_HI);
    uint32_t* pha_lo = (uint32_t*)(smem + PHA_LO);
    uint32_t* xs_hi  = (uint32_t*)(smem + XS_HI);
    uint32_t* xs_lo  = (uint32_t*)(smem + XS_LO);
    uint16_t* rs_hi16 = (uint16_t*)(smem + RS_HI);
    uint16_t* rs_lo16 = (uint16_t*)(smem + RS_LO);

    const uint32_t pha_hi_b = smem_u32(smem + PHA_HI);
    const uint32_t pha_lo_b = smem_u32(smem + PHA_LO);
    const uint32_t xs_hi_b  = smem_u32(smem + XS_HI);
    const uint32_t xs_lo_b  = smem_u32(smem + XS_LO);
    const uint32_t rs_hi_b  = smem_u32(smem + RS_HI);
    const uint32_t rs_lo_b  = smem_u32(smem + RS_LO);

    // ---------------- stage phi (hi/lo splits, native row-major) ----------------
    for (int it = tid; it < MDIM * 128; it += TPB) {
        const int m = it >> 7, kp = it & 127;
        const float2 v = *(const float2*)(phi + m * NROW + 2 * kp);
        uint16_t h0, l0, h1, l1;
        bf16_split(v.x, h0, l0);
        bf16_split(v.y, h1, l1);
        pha_hi[m * 132 + kp] = (uint32_t)h0 | ((uint32_t)h1 << 16);
        pha_lo[m * 132 + kp] = (uint32_t)l0 | ((uint32_t)l1 << 16);
    }

    // per-thread staging coordinates (8 float2 per 32-row chunk)
    int st_col[8], st_kp[8], st_gc[8];
    #pragma unroll
    for (int i = 0; i < 8; ++i) {
        const int it = tid + i * TPB;       // 0..2047
        st_col[i] = it & 127;
        st_kp[i]  = it >> 7;                // 0..15 (k-pair within chunk)
        int gc = base + st_col[i];
        st_gc[i] = (gc < K) ? gc : (K - 1);
    }

    // preload chunk 0 into registers
    float2 xr[8];
    #pragma unroll
    for (int i = 0; i < 8; ++i) {
        const int gn = 2 * st_kp[i];
        xr[i].x = X[(size_t)gn * K + st_gc[i]];
        xr[i].y = X[(size_t)(gn + 1) * K + st_gc[i]];
    }

    // ================= GEMM A: R(64 x 128) = phi . Xtile, 8 chunks of 32 rows =================
    const int mbase  = 16 * (w & 3);
    const int nbase0 = 64 * (w >> 2);
    float cA[8][4];
    #pragma unroll
    for (int nt = 0; nt < 8; ++nt)
        #pragma unroll
        for (int q = 0; q < 4; ++q) cA[nt][q] = 0.0f;

    // fragment smem addresses (lane-dependent, loop-invariant parts)
    const uint32_t a_row_off = (uint32_t)(lane & 15) * PHA_SB + (uint32_t)((lane >> 4) << 3) * 2;
    const uint32_t b_row     = (uint32_t)(lane & 7);
    const uint32_t b_koff    = (uint32_t)(((lane >> 3) & 1) << 3) * 2;

    float2 yv[16];

    #pragma unroll 1
    for (int chunk = 0; chunk < NCHUNK; ++chunk) {
        // STS current chunk from registers
        #pragma unroll
        for (int i = 0; i < 8; ++i) {
            uint16_t h0, l0, h1, l1;
            bf16_split(xr[i].x, h0, l0);
            bf16_split(xr[i].y, h1, l1);
            xs_hi[st_col[i] * XS_S32 + st_kp[i]] = (uint32_t)h0 | ((uint32_t)h1 << 16);
            xs_lo[st_col[i] * XS_S32 + st_kp[i]] = (uint32_t)l0 | ((uint32_t)l1 << 16);
        }
        __syncthreads();

        // issue next chunk's (or Y's) loads — consumed after the MMAs below
        if (chunk + 1 < NCHUNK) {
            #pragma unroll
            for (int i = 0; i < 8; ++i) {
                const int gn = (chunk + 1) * CHUNK + 2 * st_kp[i];
                xr[i].x = X[(size_t)gn * K + st_gc[i]];
                xr[i].y = X[(size_t)(gn + 1) * K + st_gc[i]];
            }
        } else {
            #pragma unroll
            for (int nt = 0; nt < 8; ++nt) {
                const int nloc = nbase0 + nt * 8 + 2 * tg;
                int col0 = base + nloc; col0 = (col0 < K - 1) ? col0 : (K - 2);
                yv[2 * nt]     = *(const float2*)(Y + (size_t)(mbase + g) * K + col0);
                yv[2 * nt + 1] = *(const float2*)(Y + (size_t)(mbase + g + 8) * K + col0);
            }
        }

        // MMA this chunk (2 k-steps of 16)
        #pragma unroll
        for (int ks = 0; ks < 2; ++ks) {
            const int k0 = chunk * CHUNK + ks * 16;
            uint32_t ah[4], al[4];
            LDMX4(ah, pha_hi_b + (uint32_t)mbase * PHA_SB + (uint32_t)k0 * 2 + a_row_off);
            LDMX4(al, pha_lo_b + (uint32_t)mbase * PHA_SB + (uint32_t)k0 * 2 + a_row_off);
            #pragma unroll
            for (int nt = 0; nt < 8; ++nt) {
                const uint32_t roff = (uint32_t)(nbase0 + nt * 8 + b_row) * XS_SB
                                    + (uint32_t)(ks * 16) * 2 + b_koff;
                uint32_t bh[2], bl[2];
                LDMX2(bh, xs_hi_b + roff);
                LDMX2(bl, xs_lo_b + roff);
                MMA_BF16(cA[nt], ah, bh[0], bh[1]);
                MMA_BF16(cA[nt], ah, bl[0], bl[1]);
                MMA_BF16(cA[nt], al, bh[0], bh[1]);
            }
        }
        __syncthreads();   // XS consumed; next chunk (or RS aliasing) may overwrite
    }

    // ---- epilogue A: r = s*(y - R) -> bf16 split -> Rs[n][m] (aliases XS) ----
    #pragma unroll
    for (int nt = 0; nt < 8; ++nt) {
        const int nloc = nbase0 + nt * 8 + 2 * tg;
        const int m0 = mbase + g, m1 = m0 + 8;
        const float2 y0 = yv[2 * nt], y1 = yv[2 * nt + 1];
        const float r00 = s * (y0.x - cA[nt][0]);
        const float r01 = s * (y0.y - cA[nt][1]);
        const float r10 = s * (y1.x - cA[nt][2]);
        const float r11 = s * (y1.y - cA[nt][3]);
        uint16_t h, l;
        bf16_split(r00, h, l); rs_hi16[nloc * 72 + m0] = h; rs_lo16[nloc * 72 + m0] = l;
        bf16_split(r01, h, l); rs_hi16[(nloc + 1) * 72 + m0] = h; rs_lo16[(nloc + 1) * 72 + m0] = l;
        bf16_split(r10, h, l); rs_hi16[nloc * 72 + m1] = h; rs_lo16[nloc * 72 + m1] = l;
        bf16_split(r11, h, l); rs_hi16[(nloc + 1) * 72 + m1] = h; rs_lo16[(nloc + 1) * 72 + m1] = l;
    }
    __syncthreads();

    // ================= GEMM B: corr(256 x 128) = phiT . R, K = 64 =================
    const int lrow = (lane & 7) + ((lane & 16) >> 1);
    const int lcol = (lane & 8);

    #pragma unroll 1
    for (int pass = 0; pass < 2; ++pass) {
        const int nb = pass * 64;
        float cB[2][8][4];
        #pragma unroll
        for (int mt = 0; mt < 2; ++mt)
            #pragma unroll
            for (int nt = 0; nt < 8; ++nt)
                #pragma unroll
                for (int q = 0; q < 4; ++q) cB[mt][nt][q] = 0.0f;

        #pragma unroll
        for (int ks = 0; ks < 4; ++ks) {
            const int k0 = ks * 16;   // phi row base (GEMM-B k)
            uint32_t ath[2][4], atl[2][4];
            #pragma unroll
            for (int mt = 0; mt < 2; ++mt) {
                const int m0 = 32 * w + 16 * mt;
                const uint32_t off = (uint32_t)((k0 + lrow) * PHA_SB + (m0 + lcol) * 2);
                LDMX4T(ath[mt], pha_hi_b + off);
                LDMX4T(atl[mt], pha_lo_b + off);
            }
            #pragma unroll
            for (int nt = 0; nt < 8; ++nt) {
                const uint32_t roff = (uint32_t)(nb + nt * 8 + b_row) * RS_SB
                                    + (uint32_t)(ks * 16) * 2 + b_koff;
                uint32_t bh[2], bl[2];
                LDMX2(bh, rs_hi_b + roff);
                LDMX2(bl, rs_lo_b + roff);
                #pragma unroll
                for (int mt = 0; mt < 2; ++mt) {
                    MMA_BF16(cB[mt][nt], ath[mt], bh[0], bh[1]);
                    MMA_BF16(cB[mt][nt], ath[mt], bl[0], bl[1]);
                    MMA_BF16(cB[mt][nt], atl[mt], bh[0], bh[1]);
                }
            }
        }

        // ---- epilogue B: out = thresh(X + corr), passthrough beyond kact ----
        #pragma unroll
        for (int mt = 0; mt < 2; ++mt) {
            #pragma unroll
            for (int nt = 0; nt < 8; ++nt) {
                const int col0 = base + nb + nt * 8 + 2 * tg;
                if (col0 + 1 >= K) continue;
                const int r0 = 32 * w + 16 * mt + g;
                const int r1 = r0 + 8;
                const float2 x0 = *(const float2*)(X + (size_t)r0 * K + col0);
                const float2 x1 = *(const float2*)(X + (size_t)r1 * K + col0);
                float u00 = x0.x + cB[mt][nt][0];
                float u01 = x0.y + cB[mt][nt][1];
                float u10 = x1.x + cB[mt][nt][2];
                float u11 = x1.y + cB[mt][nt][3];
                u00 = (fabsf(u00) > 0.1f) ? u00 : 0.0f;
                u01 = (fabsf(u01) > 0.1f) ? u01 : 0.0f;
                u10 = (fabsf(u10) > 0.1f) ? u10 : 0.0f;
                u11 = (fabsf(u11) > 0.1f) ? u11 : 0.0f;
                const bool a0 = (col0 < kact), a1 = (col0 + 1 < kact);
                float2 o0, o1;
                o0.x = a0 ? u00 : x0.x;  o0.y = a1 ? u01 : x0.y;
                o1.x = a0 ? u10 : x1.x;  o1.y = a1 ? u11 : x1.y;
                *(float2*)(outX + (size_t)r0 * K + col0) = o0;
                *(float2*)(outX + (size_t)r1 * K + col0) = o1;
            }
        }
    }
}

extern "C" void kernel_launch(void* const* d_in, const int* in_sizes, int n_in,
                              void* d_out, int out_size)
{
    const float* phi  = (const float*)d_in[0];
    const float* X    = (const float*)d_in[1];
    const float* Y    = (const float*)d_in[2];
    const float* step = (const float*)d_in[3];
    const int*   idx  = (const int*)d_in[4];

    const int phiN = in_sizes[0];
    const int XN   = in_sizes[1];
    const int K    = XN / NROW;

    float* outX = (float*)d_out;
    if (out_size == phiN + XN) {
        cudaMemcpyAsync(d_out, phi, (size_t)phiN * sizeof(float),
                        cudaMemcpyDeviceToDevice, 0);
        outX = (float*)d_out + phiN;
    }

    cudaFuncSetAttribute(ista_hmma_kernel,
                         cudaFuncAttributeMaxDynamicSharedMemorySize, SMEM_TOTAL);

    const int grid = (K + NT - 1) / NT;
    ista_hmma_kernel<<<grid, TPB, SMEM_TOTAL>>>(phi, X, Y, step, idx, outX, K);
}

// round 9
// speedup vs baseline: 1.6079x; 1.0914x over previous
#include <cuda_runtime.h>
#include <cuda_bf16.h>
#include <cstdint>
#include <math.h>

// phi (64,256) row-major, X (256,K), Y (64,K); k = idx+1 active columns.
constexpr int NROW = 256;
constexpr int MDIM = 64;
constexpr int NT   = 128;   // columns per CTA tile
constexpr int TPB  = 256;   // 8 warps

// ---- SMEM map ----
constexpr int PHA_HI = 0;       // phi [64][264] bf16 row-major (k-contig), 528B row stride
constexpr int PHA_LO = 33792;
constexpr int POOL   = 67584;
// double-buffered X chunk: buf b at POOL + b*20480 (hi at +0, lo at +10240)
constexpr int XSBUF  = 20480;
constexpr int RS_HI  = POOL;            // resid [128 cols][36 u32]; aliases XS (time-disjoint)
constexpr int RS_LO  = POOL + 18432;
constexpr int SMEM_TOTAL = POOL + 40960 + 128;   // 108672

constexpr int PHA_SB = 528;
constexpr int XS_S32 = 20;     // u32 stride (80 B)
constexpr int XS_SB  = 80;
constexpr int RS_S32 = 36;
constexpr int RS_SB  = 144;

constexpr int CHUNK = 32;
constexpr int NCHUNK = NROW / CHUNK;  // 8

__device__ __forceinline__ void bf16_split(float v, uint16_t& hi, uint16_t& lo) {
    __nv_bfloat16 h = __float2bfloat16_rn(v);
    __nv_bfloat16 l = __float2bfloat16_rn(v - __bfloat162float(h));
    hi = __bfloat16_as_ushort(h);
    lo = __bfloat16_as_ushort(l);
}
__device__ __forceinline__ uint32_t smem_u32(const void* p) {
    uint32_t a;
    asm("{ .reg .u64 t; cvta.to.shared.u64 t, %1; cvt.u32.u64 %0, t; }" : "=r"(a) : "l"(p));
    return a;
}

#define MMA_BF16(c, a, b0, b1)                                                  \
    asm volatile("mma.sync.aligned.m16n8k16.row.col.f32.bf16.bf16.f32 "         \
        "{%0,%1,%2,%3}, {%4,%5,%6,%7}, {%8,%9}, {%0,%1,%2,%3};"                 \
        : "+f"((c)[0]), "+f"((c)[1]), "+f"((c)[2]), "+f"((c)[3])                \
        : "r"((a)[0]), "r"((a)[1]), "r"((a)[2]), "r"((a)[3]), "r"(b0), "r"(b1))

#define LDMX4(r, addr)                                                          \
    asm volatile("ldmatrix.sync.aligned.m8n8.x4.shared.b16 {%0,%1,%2,%3}, [%4];"\
        : "=r"((r)[0]), "=r"((r)[1]), "=r"((r)[2]), "=r"((r)[3]) : "r"(addr))
#define LDMX4T(r, addr)                                                         \
    asm volatile("ldmatrix.sync.aligned.m8n8.x4.trans.shared.b16 {%0,%1,%2,%3}, [%4];" \
        : "=r"((r)[0]), "=r"((r)[1]), "=r"((r)[2]), "=r"((r)[3]) : "r"(addr))
#define LDMX2(r, addr)                                                          \
    asm volatile("ldmatrix.sync.aligned.m8n8.x2.shared.b16 {%0,%1}, [%2];"      \
        : "=r"((r)[0]), "=r"((r)[1]) : "r"(addr))

extern __shared__ char smem[];

__global__ __launch_bounds__(TPB, 2)
void ista_hmma_kernel(const float* __restrict__ phi,
                      const float* __restrict__ X,
                      const float* __restrict__ Y,
                      const float* __restrict__ step,
                      const int*   __restrict__ idxp,
                      float*       __restrict__ outX,
                      int K)
{
    const int tid  = threadIdx.x;
    const int w    = tid >> 5;
    const int lane = tid & 31;
    const int g    = lane >> 2;
    const int tg   = lane & 3;
    const int base = blockIdx.x * NT;
    const int kact = *idxp + 1;

    if (base >= kact) {
        const int col = base + (tid & 127);
        if (col < K) {
            for (int n = (tid >> 7); n < NROW; n += 2)
                outX[(size_t)n * K + col] = X[(size_t)n * K + col];
        }
        return;
    }

    const float s = *step;

    uint32_t* pha_hi = (uint32_t*)(smem + PHA_HI);
    uint32_t* pha_lo = (uint32_t*)(smem + PHA_LO);
    uint16_t* rs_hi16 = (uint16_t*)(smem + RS_HI);
    uint16_t* rs_lo16 = (uint16_t*)(smem + RS_LO);

    const uint32_t pha_hi_b = smem_u32(smem + PHA_HI);
    const uint32_t pha_lo_b = smem_u32(smem + PHA_LO);
    const uint32_t pool_b   = smem_u32(smem + POOL);
    const uint32_t rs_hi_b  = smem_u32(smem + RS_HI);
    const uint32_t rs_lo_b  = smem_u32(smem + RS_LO);

    // per-thread staging coordinates (8 float2 per 32-row chunk)
    int st_col[8], st_kp[8], st_gc[8];
    #pragma unroll
    for (int i = 0; i < 8; ++i) {
        const int it = tid + i * TPB;
        st_col[i] = it & 127;
        st_kp[i]  = it >> 7;
        int gc = base + st_col[i];
        st_gc[i] = (gc < K) ? gc : (K - 1);
    }

    // issue chunk-0 X loads FIRST (latency hides under phi staging below)
    float2 xr[8];
    #pragma unroll
    for (int i = 0; i < 8; ++i) {
        const int gn = 2 * st_kp[i];
        xr[i].x = X[(size_t)gn * K + st_gc[i]];
        xr[i].y = X[(size_t)(gn + 1) * K + st_gc[i]];
    }

    // ---------------- stage phi (hi/lo splits, native row-major) ----------------
    for (int it = tid; it < MDIM * 128; it += TPB) {
        const int m = it >> 7, kp = it & 127;
        const float2 v = *(const float2*)(phi + m * NROW + 2 * kp);
        uint16_t h0, l0, h1, l1;
        bf16_split(v.x, h0, l0);
        bf16_split(v.y, h1, l1);
        pha_hi[m * 132 + kp] = (uint32_t)h0 | ((uint32_t)h1 << 16);
        pha_lo[m * 132 + kp] = (uint32_t)l0 | ((uint32_t)l1 << 16);
    }

    // ================= GEMM A: R(64x128) = phi . Xtile =================
    // warp tiling 2m x 4n groups: Mw=32 (2 mt), Nw=32 (4 nt)
    const int mbase = 32 * (w & 1);
    const int nbase = 32 * (w >> 1);
    float cA[2][4][4];
    #pragma unroll
    for (int mt = 0; mt < 2; ++mt)
        #pragma unroll
        for (int nt = 0; nt < 4; ++nt)
            #pragma unroll
            for (int q = 0; q < 4; ++q) cA[mt][nt][q] = 0.0f;

    const uint32_t a_row_off = (uint32_t)(lane & 15) * PHA_SB + (uint32_t)((lane >> 4) << 3) * 2;
    const uint32_t b_row     = (uint32_t)(lane & 7);
    const uint32_t b_koff    = (uint32_t)(((lane >> 3) & 1) << 3) * 2;

    float2 yv[2][4][2];

    #pragma unroll 1
    for (int chunk = 0; chunk < NCHUNK; ++chunk) {
        const uint32_t xb = pool_b + (uint32_t)(chunk & 1) * XSBUF;
        uint32_t* xs_hi = (uint32_t*)(smem + POOL + (chunk & 1) * XSBUF);
        uint32_t* xs_lo = xs_hi + (10240 / 4);

        // STS current chunk from registers into buf[chunk&1]
        #pragma unroll
        for (int i = 0; i < 8; ++i) {
            uint16_t h0, l0, h1, l1;
            bf16_split(xr[i].x, h0, l0);
            bf16_split(xr[i].y, h1, l1);
            xs_hi[st_col[i] * XS_S32 + st_kp[i]] = (uint32_t)h0 | ((uint32_t)h1 << 16);
            xs_lo[st_col[i] * XS_S32 + st_kp[i]] = (uint32_t)l0 | ((uint32_t)l1 << 16);
        }
        __syncthreads();   // only barrier per chunk (double-buffered)

        // next chunk's (or Y's) loads — consumed next iteration / epilogue
        if (chunk + 1 < NCHUNK) {
            #pragma unroll
            for (int i = 0; i < 8; ++i) {
                const int gn = (chunk + 1) * CHUNK + 2 * st_kp[i];
                xr[i].x = X[(size_t)gn * K + st_gc[i]];
                xr[i].y = X[(size_t)(gn + 1) * K + st_gc[i]];
            }
        } else {
            #pragma unroll
            for (int mt = 0; mt < 2; ++mt)
                #pragma unroll
                for (int nt = 0; nt < 4; ++nt) {
                    const int nloc = nbase + nt * 8 + 2 * tg;
                    int col0 = base + nloc; col0 = (col0 < K - 1) ? col0 : (K - 2);
                    const int m0 = mbase + 16 * mt + g;
                    yv[mt][nt][0] = *(const float2*)(Y + (size_t)m0 * K + col0);
                    yv[mt][nt][1] = *(const float2*)(Y + (size_t)(m0 + 8) * K + col0);
                }
        }

        // MMA this chunk (2 k-steps of 16)
        #pragma unroll
        for (int ks = 0; ks < 2; ++ks) {
            const int k0 = chunk * CHUNK + ks * 16;
            uint32_t ah[2][4], al[2][4];
            #pragma unroll
            for (int mt = 0; mt < 2; ++mt) {
                const uint32_t aoff = (uint32_t)(mbase + 16 * mt) * PHA_SB
                                    + (uint32_t)k0 * 2 + a_row_off;
                LDMX4(ah[mt], pha_hi_b + aoff);
                LDMX4(al[mt], pha_lo_b + aoff);
            }
            #pragma unroll
            for (int nt = 0; nt < 4; ++nt) {
                const uint32_t roff = (uint32_t)(nbase + nt * 8 + b_row) * XS_SB
                                    + (uint32_t)(ks * 16) * 2 + b_koff;
                uint32_t bh[2], bl[2];
                LDMX2(bh, xb + roff);
                LDMX2(bl, xb + 10240 + roff);
                #pragma unroll
                for (int mt = 0; mt < 2; ++mt) {
                    MMA_BF16(cA[mt][nt], ah[mt], bh[0], bh[1]);
                    MMA_BF16(cA[mt][nt], ah[mt], bl[0], bl[1]);
                    MMA_BF16(cA[mt][nt], al[mt], bh[0], bh[1]);
                }
            }
        }
    }
    __syncthreads();   // all MMA reads of pool done before RS aliases it

    // ---- epilogue A: r = s*(y - R) -> bf16 split -> Rs[n][m] ----
    #pragma unroll
    for (int mt = 0; mt < 2; ++mt)
        #pragma unroll
        for (int nt = 0; nt < 4; ++nt) {
            const int nloc = nbase + nt * 8 + 2 * tg;
            const int m0 = mbase + 16 * mt + g, m1 = m0 + 8;
            const float2 y0 = yv[mt][nt][0], y1 = yv[mt][nt][1];
            const float r00 = s * (y0.x - cA[mt][nt][0]);
            const float r01 = s * (y0.y - cA[mt][nt][1]);
            const float r10 = s * (y1.x - cA[mt][nt][2]);
            const float r11 = s * (y1.y - cA[mt][nt][3]);
            uint16_t h, l;
            bf16_split(r00, h, l); rs_hi16[nloc * 72 + m0] = h; rs_lo16[nloc * 72 + m0] = l;
            bf16_split(r01, h, l); rs_hi16[(nloc + 1) * 72 + m0] = h; rs_lo16[(nloc + 1) * 72 + m0] = l;
            bf16_split(r10, h, l); rs_hi16[nloc * 72 + m1] = h; rs_lo16[nloc * 72 + m1] = l;
            bf16_split(r11, h, l); rs_hi16[(nloc + 1) * 72 + m1] = h; rs_lo16[(nloc + 1) * 72 + m1] = l;
        }
    __syncthreads();

    // ================= GEMM B: corr(256x128) = phiT . R, K=64 =================
    const int lrow = (lane & 7) + ((lane & 16) >> 1);
    const int lcol = (lane & 8);

    #pragma unroll 1
    for (int pass = 0; pass < 2; ++pass) {
        const int nb = pass * 64;
        float cB[2][8][4];
        #pragma unroll
        for (int mt = 0; mt < 2; ++mt)
            #pragma unroll
            for (int nt = 0; nt < 8; ++nt)
                #pragma unroll
                for (int q = 0; q < 4; ++q) cB[mt][nt][q] = 0.0f;

        #pragma unroll
        for (int ks = 0; ks < 4; ++ks) {
            const int k0 = ks * 16;
            uint32_t ath[2][4], atl[2][4];
            #pragma unroll
            for (int mt = 0; mt < 2; ++mt) {
                const int m0 = 32 * w + 16 * mt;
                const uint32_t off = (uint32_t)((k0 + lrow) * PHA_SB + (m0 + lcol) * 2);
                LDMX4T(ath[mt], pha_hi_b + off);
                LDMX4T(atl[mt], pha_lo_b + off);
            }
            #pragma unroll
            for (int nt = 0; nt < 8; ++nt) {
                const uint32_t roff = (uint32_t)(nb + nt * 8 + b_row) * RS_SB
                                    + (uint32_t)(ks * 16) * 2 + b_koff;
                uint32_t bh[2], bl[2];
                LDMX2(bh, rs_hi_b + roff);
                LDMX2(bl, rs_lo_b + roff);
                #pragma unroll
                for (int mt = 0; mt < 2; ++mt) {
                    MMA_BF16(cB[mt][nt], ath[mt], bh[0], bh[1]);
                    MMA_BF16(cB[mt][nt], ath[mt], bl[0], bl[1]);
                    MMA_BF16(cB[mt][nt], atl[mt], bh[0], bh[1]);
                }
            }
        }

        #pragma unroll
        for (int mt = 0; mt < 2; ++mt) {
            #pragma unroll
            for (int nt = 0; nt < 8; ++nt) {
                const int col0 = base + nb + nt * 8 + 2 * tg;
                if (col0 + 1 >= K) continue;
                const int r0 = 32 * w + 16 * mt + g;
                const int r1 = r0 + 8;
                const float2 x0 = *(const float2*)(X + (size_t)r0 * K + col0);
                const float2 x1 = *(const float2*)(X + (size_t)r1 * K + col0);
                float u00 = x0.x + cB[mt][nt][0];
                float u01 = x0.y + cB[mt][nt][1];
                float u10 = x1.x + cB[mt][nt][2];
                float u11 = x1.y + cB[mt][nt][3];
                u00 = (fabsf(u00) > 0.1f) ? u00 : 0.0f;
                u01 = (fabsf(u01) > 0.1f) ? u01 : 0.0f;
                u10 = (fabsf(u10) > 0.1f) ? u10 : 0.0f;
                u11 = (fabsf(u11) > 0.1f) ? u11 : 0.0f;
                const bool a0 = (col0 < kact), a1 = (col0 + 1 < kact);
                float2 o0, o1;
                o0.x = a0 ? u00 : x0.x;  o0.y = a1 ? u01 : x0.y;
                o1.x = a0 ? u10 : x1.x;  o1.y = a1 ? u11 : x1.y;
                *(float2*)(outX + (size_t)r0 * K + col0) = o0;
                *(float2*)(outX + (size_t)r1 * K + col0) = o1;
            }
        }
    }
}

extern "C" void kernel_launch(void* const* d_in, const int* in_sizes, int n_in,
                              void* d_out, int out_size)
{
    const float* phi  = (const float*)d_in[0];
    const float* X    = (const float*)d_in[1];
    const float* Y    = (const float*)d_in[2];
    const float* step = (const float*)d_in[3];
    const int*   idx  = (const int*)d_in[4];

    const int phiN = in_sizes[0];
    const int XN   = in_sizes[1];
    const int K    = XN / NROW;

    float* outX = (float*)d_out;
    if (out_size == phiN + XN) {
        cudaMemcpyAsync(d_out, phi, (size_t)phiN * sizeof(float),
                        cudaMemcpyDeviceToDevice, 0);
        outX = (float*)d_out + phiN;
    }

    cudaFuncSetAttribute(ista_hmma_kernel,
                         cudaFuncAttributeMaxDynamicSharedMemorySize, SMEM_TOTAL);

    const int grid = (K + NT - 1) / NT;
    ista_hmma_kernel<<<grid, TPB, SMEM_TOTAL>>>(phi, X, Y, step, idx, outX, K);
}